// round 3
// baseline (speedup 1.0000x reference)
#include <cuda_runtime.h>
#include <cuda_bf16.h>
#include <math.h>
#include <cstdint>

// Problem constants
#define B_   4
#define N_   10000
#define E_   100000
#define H_   8
#define FIN_ 256            // H*F
#define M_TOTAL (B_ * N_)   // 40000

// -------------------- scratch (device globals, no allocation) --------------
__device__ float    g_proj  [B_ * N_ * FIN_];
__device__ float    g_numer [B_ * N_ * FIN_];
__device__ float    g_relagg[B_ * N_ * FIN_];
__device__ float    g_se    [B_ * E_ * H_  ];
__device__ float    g_ssrc  [B_ * N_ * H_  ];
__device__ float    g_strg  [B_ * N_ * H_  ];
__device__ float    g_denom [B_ * N_ * H_  ];
__device__ unsigned g_maxu  [B_];

// -------------------- helpers ----------------------------------------------
__device__ __forceinline__ unsigned f2o(float f) {
    unsigned u = __float_as_uint(f);
    return (u & 0x80000000u) ? ~u : (u ^ 0x80000000u);
}
__device__ __forceinline__ float o2f(unsigned u) {
    return (u & 0x80000000u) ? __uint_as_float(u ^ 0x80000000u)
                             : __uint_as_float(~u);
}
__device__ __forceinline__ void red_add_v4(float* addr, float4 v) {
    asm volatile("red.global.add.v4.f32 [%0], {%1,%2,%3,%4};"
                 :: "l"(addr), "f"(v.x), "f"(v.y), "f"(v.z), "f"(v.w)
                 : "memory");
}
__device__ __forceinline__ uint32_t smem_u32(const void* p) {
    uint32_t a;
    asm("{ .reg .u64 t; cvta.to.shared.u64 t, %1; cvt.u32.u64 %0, t; }"
        : "=r"(a) : "l"(p));
    return a;
}
__device__ __forceinline__ void ldsm_x4(uint32_t& r0, uint32_t& r1,
                                        uint32_t& r2, uint32_t& r3, uint32_t addr) {
    asm volatile("ldmatrix.sync.aligned.m8n8.x4.shared.b16 {%0,%1,%2,%3}, [%4];"
                 : "=r"(r0), "=r"(r1), "=r"(r2), "=r"(r3) : "r"(addr));
}
__device__ __forceinline__ void mma_bf16(float* d, const uint32_t* a,
                                         uint32_t b0, uint32_t b1) {
    asm volatile(
        "mma.sync.aligned.m16n8k16.row.col.f32.bf16.bf16.f32 "
        "{%0,%1,%2,%3}, {%4,%5,%6,%7}, {%8,%9}, {%0,%1,%2,%3};"
        : "+f"(d[0]), "+f"(d[1]), "+f"(d[2]), "+f"(d[3])
        : "r"(a[0]), "r"(a[1]), "r"(a[2]), "r"(a[3]), "r"(b0), "r"(b1));
}

// -------------------- smem layout for MMA GEMM ------------------------------
// Row stride 264 bf16 (= 528B) -> ldmatrix 8-address phases hit 8 distinct
// 4-bank groups (row*132 mod 32 = row*4) => conflict-free.
#define STRIDE_BF 264
#define ROW_BYTES (STRIDE_BF * 2)     // 528
#define SM_A_HI 0
#define SM_A_LO (128 * ROW_BYTES)             // 67584
#define SM_B_HI (2 * 128 * ROW_BYTES)         // 135168
#define SM_B_LO (SM_B_HI + 64 * ROW_BYTES)    // 168960
#define SM_GEMM_TOTAL (SM_B_LO + 64 * ROW_BYTES)  // 202752

__device__ __forceinline__ void cvt_split(float4 v, uint2& hi, uint2& lo) {
    __nv_bfloat16 a0 = __float2bfloat16(v.x);
    __nv_bfloat16 a1 = __float2bfloat16(v.y);
    __nv_bfloat16 a2 = __float2bfloat16(v.z);
    __nv_bfloat16 a3 = __float2bfloat16(v.w);
    __nv_bfloat16 b0 = __float2bfloat16(v.x - __bfloat162float(a0));
    __nv_bfloat16 b1 = __float2bfloat16(v.y - __bfloat162float(a1));
    __nv_bfloat16 b2 = __float2bfloat16(v.z - __bfloat162float(a2));
    __nv_bfloat16 b3 = __float2bfloat16(v.w - __bfloat162float(a3));
    hi.x = (uint32_t)__bfloat16_as_ushort(a0) | ((uint32_t)__bfloat16_as_ushort(a1) << 16);
    hi.y = (uint32_t)__bfloat16_as_ushort(a2) | ((uint32_t)__bfloat16_as_ushort(a3) << 16);
    lo.x = (uint32_t)__bfloat16_as_ushort(b0) | ((uint32_t)__bfloat16_as_ushort(b1) << 16);
    lo.y = (uint32_t)__bfloat16_as_ushort(b2) | ((uint32_t)__bfloat16_as_ushort(b3) << 16);
}

// Fill A tile (128 x 256 fp32 -> bf16 hi/lo) and B tile (64 x 256).
__device__ __forceinline__ void fill_tiles(const float* __restrict__ A, int bm,
                                           const float* __restrict__ W, int bn,
                                           char* sm) {
    const int t = threadIdx.x;
    #pragma unroll 4
    for (int i = 0; i < 32; i++) {
        int idx = i * 256 + t;
        int row = idx >> 6;
        int col = (idx & 63) * 4;
        float4 v = make_float4(0.f, 0.f, 0.f, 0.f);
        int gr = bm + row;
        if (gr < M_TOTAL)
            v = *reinterpret_cast<const float4*>(A + (size_t)gr * FIN_ + col);
        uint2 hi, lo;
        cvt_split(v, hi, lo);
        uint32_t off = (uint32_t)(row * ROW_BYTES + col * 2);
        *reinterpret_cast<uint2*>(sm + SM_A_HI + off) = hi;
        *reinterpret_cast<uint2*>(sm + SM_A_LO + off) = lo;
    }
    #pragma unroll 2
    for (int i = 0; i < 16; i++) {
        int idx = i * 256 + t;
        int row = idx >> 6;
        int col = (idx & 63) * 4;
        float4 v = *reinterpret_cast<const float4*>(W + (size_t)(bn + row) * FIN_ + col);
        uint2 hi, lo;
        cvt_split(v, hi, lo);
        uint32_t off = (uint32_t)(row * ROW_BYTES + col * 2);
        *reinterpret_cast<uint2*>(sm + SM_B_HI + off) = hi;
        *reinterpret_cast<uint2*>(sm + SM_B_LO + off) = lo;
    }
}

// Core: warp-tiled 3-pass split-bf16 mainloop.
// CTA tile 128x64; 8 warps as 4(m) x 2(n); warp tile 32x32.
// acc[mt][nt][4], mt in {0,1} (16-row halves), nt in {0..3} (8-col tiles).
__device__ __forceinline__ void mma_mainloop(char* sm, float acc[2][4][4]) {
    const int t = threadIdx.x, wid = t >> 5, lane = t & 31;
    const int warp_m = (wid & 3) * 32;
    const int warp_n = (wid >> 2) * 32;
    uint32_t smb = smem_u32(sm);

    // A fragment addresses: row = warp_m + mt*16 + (lane&7) + ((lane>>3)&1)*8,
    //                       col = (lane>>4)*8
    uint32_t aRow = (uint32_t)(warp_m + (lane & 7) + ((lane >> 3) & 1) * 8);
    uint32_t aCol16 = (uint32_t)((lane >> 4) * 16);   // bytes
    uint32_t aHi0 = smb + SM_A_HI + aRow * ROW_BYTES + aCol16;
    uint32_t aLo0 = smb + SM_A_LO + aRow * ROW_BYTES + aCol16;
    // B fragment addresses (x4 covers 2 n-tiles):
    // row = warp_n + p*16 + ((lane>>4)&1)*8 + (lane&7), col = ((lane>>3)&1)*8
    uint32_t bRow = (uint32_t)(warp_n + ((lane >> 4) & 1) * 8 + (lane & 7));
    uint32_t bCol16 = (uint32_t)(((lane >> 3) & 1) * 16);
    uint32_t bHi0 = smb + SM_B_HI + bRow * ROW_BYTES + bCol16;
    uint32_t bLo0 = smb + SM_B_LO + bRow * ROW_BYTES + bCol16;

    #pragma unroll
    for (int ks = 0; ks < 16; ks++) {
        uint32_t koff = (uint32_t)(ks * 32);  // 16 cols * 2B
        uint32_t ah[2][4], al[2][4], bh[2][4], bl[2][4];
        #pragma unroll
        for (int mt = 0; mt < 2; mt++) {
            uint32_t moff = (uint32_t)(mt * 16 * ROW_BYTES);
            ldsm_x4(ah[mt][0], ah[mt][1], ah[mt][2], ah[mt][3], aHi0 + moff + koff);
            ldsm_x4(al[mt][0], al[mt][1], al[mt][2], al[mt][3], aLo0 + moff + koff);
        }
        #pragma unroll
        for (int p = 0; p < 2; p++) {
            uint32_t noff = (uint32_t)(p * 16 * ROW_BYTES);
            ldsm_x4(bh[p][0], bh[p][1], bh[p][2], bh[p][3], bHi0 + noff + koff);
            ldsm_x4(bl[p][0], bl[p][1], bl[p][2], bl[p][3], bLo0 + noff + koff);
        }
        #pragma unroll
        for (int mt = 0; mt < 2; mt++)
            #pragma unroll
            for (int p = 0; p < 2; p++)
                #pragma unroll
                for (int q = 0; q < 2; q++) {
                    int nt = p * 2 + q;
                    mma_bf16(acc[mt][nt], ah[mt], bh[p][2 * q], bh[p][2 * q + 1]);
                    mma_bf16(acc[mt][nt], ah[mt], bl[p][2 * q], bl[p][2 * q + 1]);
                    mma_bf16(acc[mt][nt], al[mt], bh[p][2 * q], bh[p][2 * q + 1]);
                }
    }
}

// -------------------- K0: zero scratch -------------------------------------
__global__ void zero_kernel() {
    int i = blockIdx.x * blockDim.x + threadIdx.x;
    int stride = gridDim.x * blockDim.x;
    float4 z = make_float4(0.f, 0.f, 0.f, 0.f);
    float4* n4 = reinterpret_cast<float4*>(g_numer);
    float4* r4 = reinterpret_cast<float4*>(g_relagg);
    const int NV = (B_ * N_ * FIN_) / 4;
    for (int j = i; j < NV; j += stride) { n4[j] = z; r4[j] = z; }
    const int ND = B_ * N_ * H_;
    for (int j = i; j < ND; j += stride) g_denom[j] = 0.f;
    if (i < B_) g_maxu[i] = 0u;
}

// -------------------- K1: proj = x @ W^T + fused s_src/s_trg ---------------
extern __shared__ char dynsm[];
__global__ void __launch_bounds__(256, 1)
gemm0_mma(const float* __restrict__ X, const float* __restrict__ W,
          const float* __restrict__ a_src, const float* __restrict__ a_trg) {
    char* sm = dynsm;
    const int t = threadIdx.x, wid = t >> 5, lane = t & 31;
    const int bm = blockIdx.y * 128, bn = blockIdx.x * 64;
    const int warp_m = (wid & 3) * 32, warp_n = (wid >> 2) * 32;

    fill_tiles(X, bm, W, bn, sm);
    __syncthreads();

    float acc[2][4][4];
    #pragma unroll
    for (int a = 0; a < 2; a++)
        #pragma unroll
        for (int b = 0; b < 4; b++)
            #pragma unroll
            for (int c = 0; c < 4; c++) acc[a][b][c] = 0.f;

    mma_mainloop(sm, acc);

    // epilogue: proj store + fused attention logits (one head per warp)
    const int h = (bn + warp_n) >> 5;
    const int colq = (lane & 3) * 2;               // within 8-col tile
    #pragma unroll
    for (int mt = 0; mt < 2; mt++) {
        int r0 = bm + warp_m + mt * 16 + (lane >> 2);
        float s_s0 = 0.f, s_t0 = 0.f, s_s8 = 0.f, s_t8 = 0.f;
        #pragma unroll
        for (int nt = 0; nt < 4; nt++) {
            int lc = nt * 8 + colq;               // 0..31 within head
            float as0 = a_src[h * 32 + lc], as1 = a_src[h * 32 + lc + 1];
            float at0 = a_trg[h * 32 + lc], at1 = a_trg[h * 32 + lc + 1];
            s_s0 += acc[mt][nt][0] * as0 + acc[mt][nt][1] * as1;
            s_t0 += acc[mt][nt][0] * at0 + acc[mt][nt][1] * at1;
            s_s8 += acc[mt][nt][2] * as0 + acc[mt][nt][3] * as1;
            s_t8 += acc[mt][nt][2] * at0 + acc[mt][nt][3] * at1;
            int gc = bn + warp_n + lc;
            if (r0 < M_TOTAL)
                *reinterpret_cast<float2*>(g_proj + (size_t)r0 * FIN_ + gc) =
                    make_float2(acc[mt][nt][0], acc[mt][nt][1]);
            if (r0 + 8 < M_TOTAL)
                *reinterpret_cast<float2*>(g_proj + (size_t)(r0 + 8) * FIN_ + gc) =
                    make_float2(acc[mt][nt][2], acc[mt][nt][3]);
        }
        #pragma unroll
        for (int o = 1; o <= 2; o <<= 1) {
            s_s0 += __shfl_xor_sync(0xFFFFFFFFu, s_s0, o);
            s_t0 += __shfl_xor_sync(0xFFFFFFFFu, s_t0, o);
            s_s8 += __shfl_xor_sync(0xFFFFFFFFu, s_s8, o);
            s_t8 += __shfl_xor_sync(0xFFFFFFFFu, s_t8, o);
        }
        if ((lane & 3) == 0) {
            if (r0 < M_TOTAL) {
                g_ssrc[r0 * H_ + h] = s_s0;
                g_strg[r0 * H_ + h] = s_t0;
            }
            if (r0 + 8 < M_TOTAL) {
                g_ssrc[(r0 + 8) * H_ + h] = s_s8;
                g_strg[(r0 + 8) * H_ + h] = s_t8;
            }
        }
    }
}

// -------------------- K3: per-edge leaky-relu score + batch max ------------
__global__ void edge_score_kernel(const int* __restrict__ EI) {
    const int b = blockIdx.y;
    const int e = blockIdx.x * 256 + threadIdx.x;
    float lmax = -INFINITY;
    if (e < E_) {
        int src = EI[b * 2 * E_ + e];
        int trg = EI[b * 2 * E_ + E_ + e];
        const float* s1 = g_ssrc + (b * N_ + src) * H_;
        const float* s2 = g_strg + (b * N_ + trg) * H_;
        float v[8];
        #pragma unroll
        for (int h = 0; h < 8; h++) {
            float s = s1[h] + s2[h];
            s = (s > 0.f) ? s : 0.2f * s;
            v[h] = s;
            lmax = fmaxf(lmax, s);
        }
        float4* sp = reinterpret_cast<float4*>(g_se + (size_t)(b * E_ + e) * H_);
        sp[0] = make_float4(v[0], v[1], v[2], v[3]);
        sp[1] = make_float4(v[4], v[5], v[6], v[7]);
    }
    #pragma unroll
    for (int o = 16; o; o >>= 1)
        lmax = fmaxf(lmax, __shfl_xor_sync(0xFFFFFFFFu, lmax, o));
    __shared__ float wmax[8];
    int lane = threadIdx.x & 31, wid = threadIdx.x >> 5;
    if (lane == 0) wmax[wid] = lmax;
    __syncthreads();
    if (threadIdx.x == 0) {
        float m = wmax[0];
        #pragma unroll
        for (int w = 1; w < 8; w++) m = fmaxf(m, wmax[w]);
        atomicMax(&g_maxu[b], f2o(m));
    }
}

// -------------------- K4: exp(s - max) + denom scatter ---------------------
__global__ void exp_denom_kernel(const int* __restrict__ EI) {
    const int b = blockIdx.y;
    const int e = blockIdx.x * 256 + threadIdx.x;
    if (e >= E_) return;
    const float mx = o2f(g_maxu[b]);
    float4* sp = reinterpret_cast<float4*>(g_se + (size_t)(b * E_ + e) * H_);
    float4 v0 = sp[0], v1 = sp[1];
    v0.x = expf(v0.x - mx); v0.y = expf(v0.y - mx);
    v0.z = expf(v0.z - mx); v0.w = expf(v0.w - mx);
    v1.x = expf(v1.x - mx); v1.y = expf(v1.y - mx);
    v1.z = expf(v1.z - mx); v1.w = expf(v1.w - mx);
    sp[0] = v0; sp[1] = v1;
    int trg = EI[b * 2 * E_ + E_ + e];
    float* d = g_denom + (b * N_ + trg) * H_;
    red_add_v4(d, v0);
    red_add_v4(d + 4, v1);
}

// -------------------- K5: fused message + rel scatter (warp per edge) ------
__global__ void scatter_kernel(const int* __restrict__ EI,
                               const float* __restrict__ rel) {
    const int b    = blockIdx.y;
    const int lane = threadIdx.x & 31;
    const int e    = blockIdx.x * 8 + (threadIdx.x >> 5);
    int src = 0, trg = 0;
    if (lane == 0) {
        src = EI[b * 2 * E_ + e];
        trg = EI[b * 2 * E_ + E_ + e];
    }
    src = __shfl_sync(0xFFFFFFFFu, src, 0);
    trg = __shfl_sync(0xFFFFFFFFu, trg, 0);

    float a = 0.f;
    if (lane < 8)
        a = g_se[(size_t)(b * E_ + e) * H_ + lane] /
            (g_denom[(b * N_ + trg) * H_ + lane] + 1e-16f);
    float att0 = __shfl_sync(0xFFFFFFFFu, a, lane >> 3);
    float att1 = __shfl_sync(0xFFFFFFFFu, a, 4 + (lane >> 3));

    const float4* prow = reinterpret_cast<const float4*>(g_proj + (size_t)(b * N_ + src) * FIN_);
    const float4* rrow = reinterpret_cast<const float4*>(rel    + (size_t)(b * E_ + e) * FIN_);
    float* nrow = g_numer  + (size_t)(b * N_ + trg) * FIN_;
    float* grow = g_relagg + (size_t)(b * N_ + trg) * FIN_;

    float4 p0 = prow[lane], p1 = prow[lane + 32];
    float4 r0 = rrow[lane], r1 = rrow[lane + 32];

    red_add_v4(nrow + 4 * lane,
               make_float4(p0.x * att0, p0.y * att0, p0.z * att0, p0.w * att0));
    red_add_v4(nrow + 128 + 4 * lane,
               make_float4(p1.x * att1, p1.y * att1, p1.z * att1, p1.w * att1));
    red_add_v4(grow + 4 * lane, r0);
    red_add_v4(grow + 128 + 4 * lane, r1);
}

// -------------------- K6: out = elu(relagg @ W^T + numer + x + bias) -------
__global__ void __launch_bounds__(256, 1)
gemm1_mma(const float* __restrict__ W, const float* __restrict__ X,
          const float* __restrict__ bias, float* __restrict__ out) {
    char* sm = dynsm;
    const int t = threadIdx.x, wid = t >> 5, lane = t & 31;
    const int bm = blockIdx.y * 128, bn = blockIdx.x * 64;
    const int warp_m = (wid & 3) * 32, warp_n = (wid >> 2) * 32;

    fill_tiles(g_relagg, bm, W, bn, sm);
    __syncthreads();

    float acc[2][4][4];
    #pragma unroll
    for (int a = 0; a < 2; a++)
        #pragma unroll
        for (int b = 0; b < 4; b++)
            #pragma unroll
            for (int c = 0; c < 4; c++) acc[a][b][c] = 0.f;

    mma_mainloop(sm, acc);

    const int colq = (lane & 3) * 2;
    #pragma unroll
    for (int mt = 0; mt < 2; mt++) {
        int r0 = bm + warp_m + mt * 16 + (lane >> 2);
        #pragma unroll
        for (int nt = 0; nt < 4; nt++) {
            int gc = bn + warp_n + nt * 8 + colq;
            #pragma unroll
            for (int half = 0; half < 2; half++) {
                int row = r0 + half * 8;
                if (row >= M_TOTAL) continue;
                float2 nm = *reinterpret_cast<const float2*>(g_numer + (size_t)row * FIN_ + gc);
                float2 xv = *reinterpret_cast<const float2*>(X + (size_t)row * FIN_ + gc);
                float2 bb = *reinterpret_cast<const float2*>(bias + gc);
                float v0 = acc[mt][nt][2 * half]     + nm.x + xv.x + bb.x;
                float v1 = acc[mt][nt][2 * half + 1] + nm.y + xv.y + bb.y;
                v0 = (v0 > 0.f) ? v0 : (expf(v0) - 1.f);
                v1 = (v1 > 0.f) ? v1 : (expf(v1) - 1.f);
                *reinterpret_cast<float2*>(out + (size_t)row * FIN_ + gc) =
                    make_float2(v0, v1);
            }
        }
    }
}

// -------------------- launch ------------------------------------------------
extern "C" void kernel_launch(void* const* d_in, const int* in_sizes, int n_in,
                              void* d_out, int out_size) {
    const float* x     = (const float*)d_in[0];
    const int*   EI    = (const int*)  d_in[1];
    const float* rel   = (const float*)d_in[2];
    const float* W     = (const float*)d_in[3];
    const float* a_src = (const float*)d_in[4];
    const float* a_trg = (const float*)d_in[5];
    const float* bias  = (const float*)d_in[6];
    float* out = (float*)d_out;

    static bool attr_done = false;
    if (!attr_done) {
        cudaFuncSetAttribute(gemm0_mma, cudaFuncAttributeMaxDynamicSharedMemorySize, SM_GEMM_TOTAL);
        cudaFuncSetAttribute(gemm1_mma, cudaFuncAttributeMaxDynamicSharedMemorySize, SM_GEMM_TOTAL);
        attr_done = true;
    }

    dim3 ggrid(FIN_ / 64, (M_TOTAL + 127) / 128);  // (4, 313)

    zero_kernel<<<2048, 256>>>();
    gemm0_mma<<<ggrid, 256, SM_GEMM_TOTAL>>>(x, W, a_src, a_trg);
    edge_score_kernel<<<dim3((E_ + 255) / 256, B_), 256>>>(EI);
    exp_denom_kernel<<<dim3((E_ + 255) / 256, B_), 256>>>(EI);
    scatter_kernel<<<dim3(E_ / 8, B_), 256>>>(EI, rel);
    gemm1_mma<<<ggrid, 256, SM_GEMM_TOTAL>>>(W, x, bias, out);
}

// round 4
// speedup vs baseline: 1.3305x; 1.3305x over previous
#include <cuda_runtime.h>
#include <math.h>
#include <cstdint>

// Problem constants
#define B_   4
#define N_   10000
#define E_   100000
#define H_   8
#define FIN_ 256
#define M_TOTAL 40000

// GEMM tiling
#define BM 128
#define BN 64
#define BK 16

// -------------------- scratch (device globals) ------------------------------
__device__ float g_proj  [M_TOTAL * FIN_];
__device__ float g_numer [M_TOTAL * FIN_];
__device__ float g_relagg[M_TOTAL * FIN_];
__device__ float g_se    [B_ * E_ * H_];
__device__ float g_ssrc  [M_TOTAL * H_];
__device__ float g_strg  [M_TOTAL * H_];
__device__ float g_denom [M_TOTAL * H_];

// -------------------- helpers ----------------------------------------------
__device__ __forceinline__ void red_add_v4(float* addr, float4 v) {
    asm volatile("red.global.add.v4.f32 [%0], {%1,%2,%3,%4};"
                 :: "l"(addr), "f"(v.x), "f"(v.y), "f"(v.z), "f"(v.w)
                 : "memory");
}

struct SmemGemm {
    float As[2][BK][BM];   // k-major, transposed on store
    float Bs[2][BK][BN];
};  // 24576 bytes

// Double-buffered 128x64 GEMM core: acc[8][4] += A[bm:bm+128,:] @ W[bn:bn+64,:]^T
__device__ __forceinline__ void gemm_tile(const float* __restrict__ A,
                                          const float* __restrict__ Wt,
                                          int bm, int bn, SmemGemm& S,
                                          float acc[8][4]) {
    const int t  = threadIdx.x;
    const int am = t & 127, ak = (t >> 7) * 8;   // A stage: row, k-offset
    const int bl = t & 63,  bk = (t >> 6) * 4;   // B stage: row, k-offset
    const int ty = t >> 4,  tx = t & 15;

    const bool aval = (bm + am) < M_TOTAL;
    const float* Arow = A  + (size_t)(bm + am) * FIN_ + ak;
    const float* Brow = Wt + (size_t)(bn + bl) * FIN_ + bk;

    float4 ra0, ra1, rb;
    const float4 fz = make_float4(0.f, 0.f, 0.f, 0.f);
    ra0 = aval ? *reinterpret_cast<const float4*>(Arow)     : fz;
    ra1 = aval ? *reinterpret_cast<const float4*>(Arow + 4) : fz;
    rb  = *reinterpret_cast<const float4*>(Brow);

    #pragma unroll 1
    for (int kb = 0; kb < FIN_ / BK; kb++) {
        const int buf = kb & 1;
        // stage -> smem (transposed)
        S.As[buf][ak + 0][am] = ra0.x; S.As[buf][ak + 1][am] = ra0.y;
        S.As[buf][ak + 2][am] = ra0.z; S.As[buf][ak + 3][am] = ra0.w;
        S.As[buf][ak + 4][am] = ra1.x; S.As[buf][ak + 5][am] = ra1.y;
        S.As[buf][ak + 6][am] = ra1.z; S.As[buf][ak + 7][am] = ra1.w;
        S.Bs[buf][bk + 0][bl] = rb.x;  S.Bs[buf][bk + 1][bl] = rb.y;
        S.Bs[buf][bk + 2][bl] = rb.z;  S.Bs[buf][bk + 3][bl] = rb.w;
        __syncthreads();
        // prefetch next k-block (overlaps compute)
        if (kb < FIN_ / BK - 1) {
            const float* An = Arow + (kb + 1) * BK;
            const float* Bn = Brow + (kb + 1) * BK;
            ra0 = aval ? *reinterpret_cast<const float4*>(An)     : fz;
            ra1 = aval ? *reinterpret_cast<const float4*>(An + 4) : fz;
            rb  = *reinterpret_cast<const float4*>(Bn);
        }
        // compute
        #pragma unroll
        for (int k = 0; k < BK; k++) {
            float4 a0 = *reinterpret_cast<const float4*>(&S.As[buf][k][ty * 8]);
            float4 a1 = *reinterpret_cast<const float4*>(&S.As[buf][k][ty * 8 + 4]);
            float4 b  = *reinterpret_cast<const float4*>(&S.Bs[buf][k][tx * 4]);
            float av[8] = {a0.x, a0.y, a0.z, a0.w, a1.x, a1.y, a1.z, a1.w};
            float bv[4] = {b.x, b.y, b.z, b.w};
            #pragma unroll
            for (int i = 0; i < 8; i++)
                #pragma unroll
                for (int j = 0; j < 4; j++)
                    acc[i][j] += av[i] * bv[j];
        }
        __syncthreads();
    }
}

// -------------------- K1: proj = x@W^T, fused scratch-zero + logits --------
__global__ void __launch_bounds__(256)
gemm0_kernel(const float* __restrict__ X, const float* __restrict__ W,
             const float* __restrict__ a_src, const float* __restrict__ a_trg) {
    __shared__ SmemGemm S;
    const int t = threadIdx.x;
    const int bm = blockIdx.y * BM, bn = blockIdx.x * BN;

    // ---- fold-in: zero g_numer / g_relagg / g_denom (independent arrays) ----
    {
        const int cta = blockIdx.y * gridDim.x + blockIdx.x;       // 0..1251
        float4 z = make_float4(0.f, 0.f, 0.f, 0.f);
        float4* n4 = reinterpret_cast<float4*>(g_numer);
        float4* r4 = reinterpret_cast<float4*>(g_relagg);
        const int NV = (M_TOTAL * FIN_) / 4;                        // 2,560,000
        #pragma unroll
        for (int i = 0; i < 8; i++) {
            int idx = cta * 2048 + i * 256 + t;
            if (idx < NV) { n4[idx] = z; r4[idx] = z; }
        }
        int di = cta * 256 + t;
        if (di < M_TOTAL * H_) g_denom[di] = 0.f;
    }

    float acc[8][4];
    #pragma unroll
    for (int i = 0; i < 8; i++)
        #pragma unroll
        for (int j = 0; j < 4; j++) acc[i][j] = 0.f;

    gemm_tile(X, W, bm, bn, S, acc);

    // ---- epilogue: store proj + fused s_src/s_trg ----
    const int ty = t >> 4, tx = t & 15;
    const int h = (bn >> 5) + (tx >> 3);                 // head for this col-quad
    float4 asv = *reinterpret_cast<const float4*>(a_src + h * 32 + (tx & 7) * 4);
    float4 atv = *reinterpret_cast<const float4*>(a_trg + h * 32 + (tx & 7) * 4);

    #pragma unroll
    for (int i = 0; i < 8; i++) {
        int row = bm + ty * 8 + i;
        bool ok = row < M_TOTAL;
        if (ok)
            *reinterpret_cast<float4*>(g_proj + (size_t)row * FIN_ + bn + tx * 4) =
                make_float4(acc[i][0], acc[i][1], acc[i][2], acc[i][3]);
        float ss = acc[i][0] * asv.x + acc[i][1] * asv.y +
                   acc[i][2] * asv.z + acc[i][3] * asv.w;
        float st = acc[i][0] * atv.x + acc[i][1] * atv.y +
                   acc[i][2] * atv.z + acc[i][3] * atv.w;
        #pragma unroll
        for (int o = 1; o <= 4; o <<= 1) {
            ss += __shfl_xor_sync(0xFFFFFFFFu, ss, o);
            st += __shfl_xor_sync(0xFFFFFFFFu, st, o);
        }
        if (ok && (tx & 7) == 0) {
            g_ssrc[row * H_ + h] = ss;
            g_strg[row * H_ + h] = st;
        }
    }
}

// -------------------- K2: edge scores -> exp -> denom scatter (no max) -----
__device__ __forceinline__ float lrexp(float s) {
    return __expf((s > 0.f) ? s : 0.2f * s);
}
__global__ void edge_fused_kernel(const int* __restrict__ EI) {
    const int b = blockIdx.y;
    const int e = blockIdx.x * 256 + threadIdx.x;
    if (e >= E_) return;
    int src = EI[b * 2 * E_ + e];
    int trg = EI[b * 2 * E_ + E_ + e];
    const float4* s1 = reinterpret_cast<const float4*>(g_ssrc + (b * N_ + src) * H_);
    const float4* s2 = reinterpret_cast<const float4*>(g_strg + (b * N_ + trg) * H_);
    float4 u0 = s1[0], u1 = s1[1], v0 = s2[0], v1 = s2[1];
    float4 w0, w1;
    w0.x = lrexp(u0.x + v0.x); w0.y = lrexp(u0.y + v0.y);
    w0.z = lrexp(u0.z + v0.z); w0.w = lrexp(u0.w + v0.w);
    w1.x = lrexp(u1.x + v1.x); w1.y = lrexp(u1.y + v1.y);
    w1.z = lrexp(u1.z + v1.z); w1.w = lrexp(u1.w + v1.w);
    float4* sp = reinterpret_cast<float4*>(g_se + (size_t)(b * E_ + e) * H_);
    sp[0] = w0; sp[1] = w1;
    float* d = g_denom + (b * N_ + trg) * H_;
    red_add_v4(d, w0);
    red_add_v4(d + 4, w1);
}

// -------------------- K3: fused message + rel scatter (warp per edge) ------
__global__ void scatter_kernel(const int* __restrict__ EI,
                               const float* __restrict__ rel) {
    const int b    = blockIdx.y;
    const int lane = threadIdx.x & 31;
    const int e    = blockIdx.x * 8 + (threadIdx.x >> 5);
    int src = 0, trg = 0;
    if (lane == 0) {
        src = EI[b * 2 * E_ + e];
        trg = EI[b * 2 * E_ + E_ + e];
    }
    src = __shfl_sync(0xFFFFFFFFu, src, 0);
    trg = __shfl_sync(0xFFFFFFFFu, trg, 0);

    float a = 0.f;
    if (lane < 8)
        a = g_se[(size_t)(b * E_ + e) * H_ + lane] /
            (g_denom[(b * N_ + trg) * H_ + lane] + 1e-16f);
    float att0 = __shfl_sync(0xFFFFFFFFu, a, lane >> 3);
    float att1 = __shfl_sync(0xFFFFFFFFu, a, 4 + (lane >> 3));

    const float4* prow = reinterpret_cast<const float4*>(g_proj + (size_t)(b * N_ + src) * FIN_);
    const float4* rrow = reinterpret_cast<const float4*>(rel    + (size_t)(b * E_ + e) * FIN_);
    float* nrow = g_numer  + (size_t)(b * N_ + trg) * FIN_;
    float* grow = g_relagg + (size_t)(b * N_ + trg) * FIN_;

    float4 p0 = prow[lane], p1 = prow[lane + 32];
    float4 r0 = rrow[lane], r1 = rrow[lane + 32];

    red_add_v4(nrow + 4 * lane,
               make_float4(p0.x * att0, p0.y * att0, p0.z * att0, p0.w * att0));
    red_add_v4(nrow + 128 + 4 * lane,
               make_float4(p1.x * att1, p1.y * att1, p1.z * att1, p1.w * att1));
    red_add_v4(grow + 4 * lane, r0);
    red_add_v4(grow + 128 + 4 * lane, r1);
}

// -------------------- K4: out = elu(relagg@W^T + numer + x + bias) ---------
__global__ void __launch_bounds__(256)
gemm1_kernel(const float* __restrict__ W, const float* __restrict__ X,
             const float* __restrict__ bias, float* __restrict__ out) {
    __shared__ SmemGemm S;
    const int t = threadIdx.x;
    const int bm = blockIdx.y * BM, bn = blockIdx.x * BN;

    float acc[8][4];
    #pragma unroll
    for (int i = 0; i < 8; i++)
        #pragma unroll
        for (int j = 0; j < 4; j++) acc[i][j] = 0.f;

    gemm_tile(g_relagg, W, bm, bn, S, acc);

    const int ty = t >> 4, tx = t & 15;
    const int col = bn + tx * 4;
    float4 bb = *reinterpret_cast<const float4*>(bias + col);
    #pragma unroll
    for (int i = 0; i < 8; i++) {
        int row = bm + ty * 8 + i;
        if (row >= M_TOTAL) continue;
        float4 nm = *reinterpret_cast<const float4*>(g_numer + (size_t)row * FIN_ + col);
        float4 xv = *reinterpret_cast<const float4*>(X + (size_t)row * FIN_ + col);
        float v0 = acc[i][0] + nm.x + xv.x + bb.x;
        float v1 = acc[i][1] + nm.y + xv.y + bb.y;
        float v2 = acc[i][2] + nm.z + xv.z + bb.z;
        float v3 = acc[i][3] + nm.w + xv.w + bb.w;
        v0 = (v0 > 0.f) ? v0 : (__expf(v0) - 1.f);
        v1 = (v1 > 0.f) ? v1 : (__expf(v1) - 1.f);
        v2 = (v2 > 0.f) ? v2 : (__expf(v2) - 1.f);
        v3 = (v3 > 0.f) ? v3 : (__expf(v3) - 1.f);
        *reinterpret_cast<float4*>(out + (size_t)row * FIN_ + col) =
            make_float4(v0, v1, v2, v3);
    }
}

// -------------------- launch ------------------------------------------------
extern "C" void kernel_launch(void* const* d_in, const int* in_sizes, int n_in,
                              void* d_out, int out_size) {
    const float* x     = (const float*)d_in[0];
    const int*   EI    = (const int*)  d_in[1];
    const float* rel   = (const float*)d_in[2];
    const float* W     = (const float*)d_in[3];
    const float* a_src = (const float*)d_in[4];
    const float* a_trg = (const float*)d_in[5];
    const float* bias  = (const float*)d_in[6];
    float* out = (float*)d_out;

    dim3 ggrid(FIN_ / BN, (M_TOTAL + BM - 1) / BM);   // (4, 313)

    gemm0_kernel<<<ggrid, 256>>>(x, W, a_src, a_trg);
    edge_fused_kernel<<<dim3((E_ + 255) / 256, B_), 256>>>(EI);
    scatter_kernel<<<dim3(E_ / 8, B_), 256>>>(EI, rel);
    gemm1_kernel<<<ggrid, 256>>>(W, x, bias, out);
}

// round 5
// speedup vs baseline: 1.4714x; 1.1059x over previous
#include <cuda_runtime.h>
#include <math.h>
#include <cstdint>

// Problem constants
#define B_   4
#define N_   10000
#define E_   100000
#define H_   8
#define FIN_ 256
#define M_TOTAL 40000

// GEMM tiling
#define BM 128
#define BN 128
#define BK 16

// -------------------- scratch (device globals) ------------------------------
__device__ float g_proj  [M_TOTAL * FIN_];
__device__ float g_numer [M_TOTAL * FIN_];
__device__ float g_relagg[M_TOTAL * FIN_];
__device__ float g_se    [B_ * E_ * H_];
__device__ float g_ssrc  [M_TOTAL * H_];
__device__ float g_strg  [M_TOTAL * H_];
__device__ float g_denom [M_TOTAL * H_];

// -------------------- helpers ----------------------------------------------
__device__ __forceinline__ void red_add_v4(float* addr, float4 v) {
    asm volatile("red.global.add.v4.f32 [%0], {%1,%2,%3,%4};"
                 :: "l"(addr), "f"(v.x), "f"(v.y), "f"(v.z), "f"(v.w)
                 : "memory");
}

struct SmemGemm {
    float As[2][BK][BM];
    float Bs[2][BK][BN];
};  // 32768 bytes

// 128x128 double-buffered GEMM core, 8x8 microtile (split 4+4 fragments).
// acc[i][j]: rows {ty*4+0..3, 64+ty*4+0..3}, cols {tx*4+0..3, 64+tx*4+0..3}
__device__ __forceinline__ void gemm_tile(const float* __restrict__ A,
                                          const float* __restrict__ Wt,
                                          int bm, int bn, SmemGemm& S,
                                          float acc[8][8]) {
    const int t  = threadIdx.x;
    const int lr = t & 127, lk = (t >> 7) * 8;   // stage: row, k-offset (both tiles)
    const int ty = t >> 4,  tx = t & 15;

    const bool aval = (bm + lr) < M_TOTAL;
    const float* Arow = A  + (size_t)(bm + lr) * FIN_ + lk;
    const float* Brow = Wt + (size_t)(bn + lr) * FIN_ + lk;

    const float4 fz = make_float4(0.f, 0.f, 0.f, 0.f);
    float4 ra0 = aval ? *reinterpret_cast<const float4*>(Arow)     : fz;
    float4 ra1 = aval ? *reinterpret_cast<const float4*>(Arow + 4) : fz;
    float4 rb0 = *reinterpret_cast<const float4*>(Brow);
    float4 rb1 = *reinterpret_cast<const float4*>(Brow + 4);

    #pragma unroll 1
    for (int kb = 0; kb < FIN_ / BK; kb++) {
        const int buf = kb & 1;
        S.As[buf][lk + 0][lr] = ra0.x; S.As[buf][lk + 1][lr] = ra0.y;
        S.As[buf][lk + 2][lr] = ra0.z; S.As[buf][lk + 3][lr] = ra0.w;
        S.As[buf][lk + 4][lr] = ra1.x; S.As[buf][lk + 5][lr] = ra1.y;
        S.As[buf][lk + 6][lr] = ra1.z; S.As[buf][lk + 7][lr] = ra1.w;
        S.Bs[buf][lk + 0][lr] = rb0.x; S.Bs[buf][lk + 1][lr] = rb0.y;
        S.Bs[buf][lk + 2][lr] = rb0.z; S.Bs[buf][lk + 3][lr] = rb0.w;
        S.Bs[buf][lk + 4][lr] = rb1.x; S.Bs[buf][lk + 5][lr] = rb1.y;
        S.Bs[buf][lk + 6][lr] = rb1.z; S.Bs[buf][lk + 7][lr] = rb1.w;
        __syncthreads();
        if (kb < FIN_ / BK - 1) {
            const float* An = Arow + (kb + 1) * BK;
            const float* Bn = Brow + (kb + 1) * BK;
            ra0 = aval ? *reinterpret_cast<const float4*>(An)     : fz;
            ra1 = aval ? *reinterpret_cast<const float4*>(An + 4) : fz;
            rb0 = *reinterpret_cast<const float4*>(Bn);
            rb1 = *reinterpret_cast<const float4*>(Bn + 4);
        }
        #pragma unroll
        for (int k = 0; k < BK; k++) {
            float4 a0 = *reinterpret_cast<const float4*>(&S.As[buf][k][ty * 4]);
            float4 a1 = *reinterpret_cast<const float4*>(&S.As[buf][k][64 + ty * 4]);
            float4 b0 = *reinterpret_cast<const float4*>(&S.Bs[buf][k][tx * 4]);
            float4 b1 = *reinterpret_cast<const float4*>(&S.Bs[buf][k][64 + tx * 4]);
            float av[8] = {a0.x, a0.y, a0.z, a0.w, a1.x, a1.y, a1.z, a1.w};
            float bv[8] = {b0.x, b0.y, b0.z, b0.w, b1.x, b1.y, b1.z, b1.w};
            #pragma unroll
            for (int i = 0; i < 8; i++)
                #pragma unroll
                for (int j = 0; j < 8; j++)
                    acc[i][j] += av[i] * bv[j];
        }
        __syncthreads();
    }
}

__device__ __forceinline__ int acc_row(int bm, int ty, int i) {
    return bm + ((i < 4) ? (ty * 4 + i) : (64 + ty * 4 + (i - 4)));
}

// -------------------- K1: proj = x@W^T, fused scratch-zero + logits --------
__global__ void __launch_bounds__(256)
gemm0_kernel(const float* __restrict__ X, const float* __restrict__ W,
             const float* __restrict__ a_src, const float* __restrict__ a_trg) {
    __shared__ SmemGemm S;
    const int t = threadIdx.x;
    const int bm = blockIdx.y * BM, bn = blockIdx.x * BN;

    // ---- fold-in: zero g_numer / g_relagg / g_denom ----
    {
        const int cta = blockIdx.y * gridDim.x + blockIdx.x;   // 0..625
        float4 z = make_float4(0.f, 0.f, 0.f, 0.f);
        float4* n4 = reinterpret_cast<float4*>(g_numer);
        float4* r4 = reinterpret_cast<float4*>(g_relagg);
        const int NV = (M_TOTAL * FIN_) / 4;                   // 2,560,000
        #pragma unroll
        for (int i = 0; i < 16; i++) {
            int idx = cta * 4096 + i * 256 + t;
            if (idx < NV) { n4[idx] = z; r4[idx] = z; }
        }
        #pragma unroll
        for (int i = 0; i < 2; i++) {
            int di = cta * 512 + i * 256 + t;
            if (di < M_TOTAL * H_) g_denom[di] = 0.f;
        }
    }

    float acc[8][8];
    #pragma unroll
    for (int i = 0; i < 8; i++)
        #pragma unroll
        for (int j = 0; j < 8; j++) acc[i][j] = 0.f;

    gemm_tile(X, W, bm, bn, S, acc);

    // ---- epilogue: store proj + fused s_src/s_trg ----
    const int ty = t >> 4, tx = t & 15;
    const int h0 = (bn >> 5) + (tx >> 3);        // head of col block 0
    const int h1 = h0 + 2;                       // head of col block 1 (+64 cols)
    const int cq = (tx & 7) * 4;                 // col-within-head
    float4 as0 = *reinterpret_cast<const float4*>(a_src + h0 * 32 + cq);
    float4 at0 = *reinterpret_cast<const float4*>(a_trg + h0 * 32 + cq);
    float4 as1 = *reinterpret_cast<const float4*>(a_src + h1 * 32 + cq);
    float4 at1 = *reinterpret_cast<const float4*>(a_trg + h1 * 32 + cq);

    #pragma unroll
    for (int i = 0; i < 8; i++) {
        int row = acc_row(bm, ty, i);
        bool ok = row < M_TOTAL;
        if (ok) {
            *reinterpret_cast<float4*>(g_proj + (size_t)row * FIN_ + bn + tx * 4) =
                make_float4(acc[i][0], acc[i][1], acc[i][2], acc[i][3]);
            *reinterpret_cast<float4*>(g_proj + (size_t)row * FIN_ + bn + 64 + tx * 4) =
                make_float4(acc[i][4], acc[i][5], acc[i][6], acc[i][7]);
        }
        float ss0 = acc[i][0] * as0.x + acc[i][1] * as0.y + acc[i][2] * as0.z + acc[i][3] * as0.w;
        float st0 = acc[i][0] * at0.x + acc[i][1] * at0.y + acc[i][2] * at0.z + acc[i][3] * at0.w;
        float ss1 = acc[i][4] * as1.x + acc[i][5] * as1.y + acc[i][6] * as1.z + acc[i][7] * as1.w;
        float st1 = acc[i][4] * at1.x + acc[i][5] * at1.y + acc[i][6] * at1.z + acc[i][7] * at1.w;
        #pragma unroll
        for (int o = 1; o <= 4; o <<= 1) {
            ss0 += __shfl_xor_sync(0xFFFFFFFFu, ss0, o);
            st0 += __shfl_xor_sync(0xFFFFFFFFu, st0, o);
            ss1 += __shfl_xor_sync(0xFFFFFFFFu, ss1, o);
            st1 += __shfl_xor_sync(0xFFFFFFFFu, st1, o);
        }
        if (ok && (tx & 7) == 0) {
            g_ssrc[row * H_ + h0] = ss0;
            g_strg[row * H_ + h0] = st0;
            g_ssrc[row * H_ + h1] = ss1;
            g_strg[row * H_ + h1] = st1;
        }
    }
}

// -------------------- K2: edge scores -> exp -> denom scatter (no max) -----
__device__ __forceinline__ float lrexp(float s) {
    return __expf((s > 0.f) ? s : 0.2f * s);
}
__global__ void edge_fused_kernel(const int* __restrict__ EI) {
    const int b = blockIdx.y;
    const int e = blockIdx.x * 256 + threadIdx.x;
    if (e >= E_) return;
    int src = EI[b * 2 * E_ + e];
    int trg = EI[b * 2 * E_ + E_ + e];
    const float4* s1 = reinterpret_cast<const float4*>(g_ssrc + (b * N_ + src) * H_);
    const float4* s2 = reinterpret_cast<const float4*>(g_strg + (b * N_ + trg) * H_);
    float4 u0 = s1[0], u1 = s1[1], v0 = s2[0], v1 = s2[1];
    float4 w0, w1;
    w0.x = lrexp(u0.x + v0.x); w0.y = lrexp(u0.y + v0.y);
    w0.z = lrexp(u0.z + v0.z); w0.w = lrexp(u0.w + v0.w);
    w1.x = lrexp(u1.x + v1.x); w1.y = lrexp(u1.y + v1.y);
    w1.z = lrexp(u1.z + v1.z); w1.w = lrexp(u1.w + v1.w);
    float4* sp = reinterpret_cast<float4*>(g_se + (size_t)(b * E_ + e) * H_);
    sp[0] = w0; sp[1] = w1;
    float* d = g_denom + (b * N_ + trg) * H_;
    red_add_v4(d, w0);
    red_add_v4(d + 4, w1);
}

// -------------------- K3: fused message + rel scatter (warp per edge) ------
__global__ void scatter_kernel(const int* __restrict__ EI,
                               const float* __restrict__ rel) {
    const int b    = blockIdx.y;
    const int lane = threadIdx.x & 31;
    const int e    = blockIdx.x * 8 + (threadIdx.x >> 5);
    int src = 0, trg = 0;
    if (lane == 0) {
        src = EI[b * 2 * E_ + e];
        trg = EI[b * 2 * E_ + E_ + e];
    }
    src = __shfl_sync(0xFFFFFFFFu, src, 0);
    trg = __shfl_sync(0xFFFFFFFFu, trg, 0);

    float a = 0.f;
    if (lane < 8)
        a = g_se[(size_t)(b * E_ + e) * H_ + lane] /
            (g_denom[(b * N_ + trg) * H_ + lane] + 1e-16f);
    float att0 = __shfl_sync(0xFFFFFFFFu, a, lane >> 3);
    float att1 = __shfl_sync(0xFFFFFFFFu, a, 4 + (lane >> 3));

    const float4* prow = reinterpret_cast<const float4*>(g_proj + (size_t)(b * N_ + src) * FIN_);
    const float4* rrow = reinterpret_cast<const float4*>(rel    + (size_t)(b * E_ + e) * FIN_);
    float* nrow = g_numer  + (size_t)(b * N_ + trg) * FIN_;
    float* grow = g_relagg + (size_t)(b * N_ + trg) * FIN_;

    float4 p0 = prow[lane], p1 = prow[lane + 32];
    float4 r0 = rrow[lane], r1 = rrow[lane + 32];

    red_add_v4(nrow + 4 * lane,
               make_float4(p0.x * att0, p0.y * att0, p0.z * att0, p0.w * att0));
    red_add_v4(nrow + 128 + 4 * lane,
               make_float4(p1.x * att1, p1.y * att1, p1.z * att1, p1.w * att1));
    red_add_v4(grow + 4 * lane, r0);
    red_add_v4(grow + 128 + 4 * lane, r1);
}

// -------------------- K4: out = elu(relagg@W^T + numer + x + bias) ---------
__global__ void __launch_bounds__(256)
gemm1_kernel(const float* __restrict__ W, const float* __restrict__ X,
             const float* __restrict__ bias, float* __restrict__ out) {
    __shared__ SmemGemm S;
    const int t = threadIdx.x;
    const int bm = blockIdx.y * BM, bn = blockIdx.x * BN;

    float acc[8][8];
    #pragma unroll
    for (int i = 0; i < 8; i++)
        #pragma unroll
        for (int j = 0; j < 8; j++) acc[i][j] = 0.f;

    gemm_tile(g_relagg, W, bm, bn, S, acc);

    const int ty = t >> 4, tx = t & 15;
    const int c0 = bn + tx * 4, c1 = bn + 64 + tx * 4;
    float4 bb0 = *reinterpret_cast<const float4*>(bias + c0);
    float4 bb1 = *reinterpret_cast<const float4*>(bias + c1);
    #pragma unroll
    for (int i = 0; i < 8; i++) {
        int row = acc_row(bm, ty, i);
        if (row >= M_TOTAL) continue;
        #pragma unroll
        for (int half = 0; half < 2; half++) {
            int col = half ? c1 : c0;
            float4 bbv = half ? bb1 : bb0;
            const float* ap = &acc[i][half * 4];
            float4 nm = *reinterpret_cast<const float4*>(g_numer + (size_t)row * FIN_ + col);
            float4 xv = *reinterpret_cast<const float4*>(X + (size_t)row * FIN_ + col);
            float v0 = ap[0] + nm.x + xv.x + bbv.x;
            float v1 = ap[1] + nm.y + xv.y + bbv.y;
            float v2 = ap[2] + nm.z + xv.z + bbv.z;
            float v3 = ap[3] + nm.w + xv.w + bbv.w;
            v0 = (v0 > 0.f) ? v0 : (__expf(v0) - 1.f);
            v1 = (v1 > 0.f) ? v1 : (__expf(v1) - 1.f);
            v2 = (v2 > 0.f) ? v2 : (__expf(v2) - 1.f);
            v3 = (v3 > 0.f) ? v3 : (__expf(v3) - 1.f);
            *reinterpret_cast<float4*>(out + (size_t)row * FIN_ + col) =
                make_float4(v0, v1, v2, v3);
        }
    }
}

// -------------------- launch ------------------------------------------------
extern "C" void kernel_launch(void* const* d_in, const int* in_sizes, int n_in,
                              void* d_out, int out_size) {
    const float* x     = (const float*)d_in[0];
    const int*   EI    = (const int*)  d_in[1];
    const float* rel   = (const float*)d_in[2];
    const float* W     = (const float*)d_in[3];
    const float* a_src = (const float*)d_in[4];
    const float* a_trg = (const float*)d_in[5];
    const float* bias  = (const float*)d_in[6];
    float* out = (float*)d_out;

    dim3 ggrid(FIN_ / BN, (M_TOTAL + BM - 1) / BM);   // (2, 313)

    gemm0_kernel<<<ggrid, 256>>>(x, W, a_src, a_trg);
    edge_fused_kernel<<<dim3((E_ + 255) / 256, B_), 256>>>(EI);
    scatter_kernel<<<dim3(E_ / 8, B_), 256>>>(EI, rel);
    gemm1_kernel<<<ggrid, 256>>>(W, x, bias, out);
}